// round 3
// baseline (speedup 1.0000x reference)
#include <cuda_runtime.h>
#include <cstdint>

// ============================================================
// BinaryDense: out[M,N] = sign(x)[M,K] @ sign(W)[K,N] + bias[N]
// M=8192, K=2048, N=2048, fp32 in/out.
// Path: int8 +-1 operands, mma.sync.m16n8k32.s8 (baseline PTX,
// no sm_103a-gated features -- tcgen05 is rejected by this
// harness's ptxas target).  s32 accum is exact (|acc| <= 2048).
// ============================================================

#define DIM_M 8192
#define DIM_K 2048
#define DIM_N 2048

static constexpr int BM = 128;
static constexpr int BN = 128;
static constexpr int BK = 64;               // int8 K-chunk: 64B rows in smem
static constexpr int STAGES = 4;
static constexpr int NITER = DIM_K / BK;    // 32
static constexpr int STAGE_BYTES = (BM + BN) * BK;   // 16384
static constexpr int SMEM_TOTAL = STAGES * STAGE_BYTES;  // 65536

// sign scratch (device globals; no allocation allowed)
__device__ int8_t g_Xb[(size_t)DIM_M * DIM_K];   // 16MB, [m][k]
__device__ int8_t g_Wt[(size_t)DIM_N * DIM_K];   // 4MB,  [n][k] (transposed W)

// ---------------- helpers ----------------

__device__ __forceinline__ uint32_t smem_u32(const void* p) {
    uint32_t a;
    asm("{ .reg .u64 t; cvta.to.shared.u64 t, %1; cvt.u32.u64 %0, t; }" : "=r"(a) : "l"(p));
    return a;
}

__device__ __forceinline__ constexpr int swz(int r) {
    // permutes the 4 16B-chunks of a 64B row; 8 consecutive rows hit 8
    // distinct 16B bank-groups -> conflict-free ldmatrix
    return (r & 3) ^ ((r >> 2) & 1);
}

__device__ __forceinline__ void cp_async16(uint32_t dst, const void* src) {
    asm volatile("cp.async.cg.shared.global [%0], [%1], 16;" :: "r"(dst), "l"(src));
}

#define CP_COMMIT() asm volatile("cp.async.commit_group;" ::: "memory")
#define CP_WAIT(n)  asm volatile("cp.async.wait_group %0;" :: "n"(n) : "memory")

#define LDSM_X4(r0, r1, r2, r3, addr) \
    asm volatile("ldmatrix.sync.aligned.m8n8.x4.shared.b16 {%0,%1,%2,%3}, [%4];" \
                 : "=r"(r0), "=r"(r1), "=r"(r2), "=r"(r3) : "r"(addr))

#define LDSM_X2(r0, r1, addr) \
    asm volatile("ldmatrix.sync.aligned.m8n8.x2.shared.b16 {%0,%1}, [%2];" \
                 : "=r"(r0), "=r"(r1) : "r"(addr))

__device__ __forceinline__ void mma_s8(int* d, const uint32_t* a, const uint32_t* b) {
    asm volatile(
        "mma.sync.aligned.m16n8k32.row.col.s32.s8.s8.s32 "
        "{%0,%1,%2,%3}, {%4,%5,%6,%7}, {%8,%9}, {%0,%1,%2,%3};"
        : "+r"(d[0]), "+r"(d[1]), "+r"(d[2]), "+r"(d[3])
        : "r"(a[0]), "r"(a[1]), "r"(a[2]), "r"(a[3]), "r"(b[0]), "r"(b[1]));
}

// ---------------- conversion kernels ----------------

// x fp32 -> int8 sign (+1 / -1).  x >= 0 (incl -0.0) -> +1.
__global__ void convert_x_kernel(const float* __restrict__ x) {
    size_t i = (size_t)blockIdx.x * blockDim.x + threadIdx.x;  // one float4
    float4 v = reinterpret_cast<const float4*>(x)[i];
    uint32_t p = (v.x < 0.0f ? 0xFFu : 0x01u)
               | ((v.y < 0.0f ? 0xFFu : 0x01u) << 8)
               | ((v.z < 0.0f ? 0xFFu : 0x01u) << 16)
               | ((v.w < 0.0f ? 0xFFu : 0x01u) << 24);
    reinterpret_cast<uint32_t*>(g_Xb)[i] = p;
}

// W[k][n] fp32 -> Wt[n][k] int8 sign (32x32 smem transpose)
__global__ void convert_w_kernel(const float* __restrict__ W) {
    __shared__ float t[32][33];
    int n0 = blockIdx.x * 32, k0 = blockIdx.y * 32;
    int tx = threadIdx.x, ty = threadIdx.y;   // blockDim (32, 8)
#pragma unroll
    for (int j = 0; j < 32; j += 8)
        t[ty + j][tx] = W[(size_t)(k0 + ty + j) * DIM_N + n0 + tx];
    __syncthreads();
#pragma unroll
    for (int j = 0; j < 32; j += 8) {
        float v = t[tx][ty + j];   // = W[k0+tx][n0+ty+j]
        g_Wt[(size_t)(n0 + ty + j) * DIM_K + k0 + tx] = (v < 0.0f) ? (int8_t)-1 : (int8_t)1;
    }
}

// ---------------- GEMM kernel ----------------

__global__ void __launch_bounds__(256, 2)
gemm_kernel(const float* __restrict__ bias, float* __restrict__ out) {
    extern __shared__ char smem[];
    const uint32_t sbase = smem_u32(smem);
    const int tid = threadIdx.x;
    const int w = tid >> 5, l = tid & 31;
    const int m0 = blockIdx.y * BM;
    const int n0 = blockIdx.x * BN;
    const int warp_m = (w >> 2) * 64;   // 2x4 warp grid: 64x32 per warp
    const int warp_n = (w & 3) * 32;

    const int8_t* Xp = g_Xb + (size_t)m0 * DIM_K;
    const int8_t* Wp = g_Wt + (size_t)n0 * DIM_K;

    // ldmatrix per-lane address offsets within a stage (k-step 0; step 1 = ^32)
    uint32_t aoff[4], boff[4];
#pragma unroll
    for (int mi = 0; mi < 4; ++mi) {
        int r  = warp_m + mi * 16 + (l & 15);
        int c4 = (l >> 4);                      // lanes 0-15: kB 0-15, 16-31: kB 16-31
        aoff[mi] = (uint32_t)(r * 64 + ((c4 ^ swz(r)) << 4));
    }
#pragma unroll
    for (int ni = 0; ni < 4; ++ni) {
        int r  = warp_n + ni * 8 + (l & 7);
        int c4 = ((l >> 3) & 1);                // lanes 0-7: kB 0-15, 8-15: kB 16-31
        boff[ni] = (uint32_t)(BM * BK + r * 64 + ((c4 ^ swz(r)) << 4));
    }

    // cp.async per-thread assignments: 2 A chunks + 2 B chunks per thread
    const int ld_c4 = tid & 3;
    const int ld_r0 = tid >> 2;              // rows ld_r0 and ld_r0+64

    auto load_stage = [&](int kt, int st) {
        const uint32_t ab = sbase + st * STAGE_BYTES;
        const int kb = kt * BK;
#pragma unroll
        for (int i = 0; i < 2; ++i) {
            int row = ld_r0 + i * 64;
            cp_async16(ab + row * 64 + ((ld_c4 ^ swz(row)) << 4),
                       Xp + (size_t)row * DIM_K + kb + ld_c4 * 16);
        }
#pragma unroll
        for (int i = 0; i < 2; ++i) {
            int row = ld_r0 + i * 64;
            cp_async16(ab + BM * BK + row * 64 + ((ld_c4 ^ swz(row)) << 4),
                       Wp + (size_t)row * DIM_K + kb + ld_c4 * 16);
        }
    };

    // prologue: fill STAGES-1 stages
#pragma unroll
    for (int s = 0; s < STAGES - 1; ++s) { load_stage(s, s); CP_COMMIT(); }

    int acc[4][4][4];
#pragma unroll
    for (int mi = 0; mi < 4; ++mi)
#pragma unroll
        for (int ni = 0; ni < 4; ++ni)
#pragma unroll
            for (int c = 0; c < 4; ++c) acc[mi][ni][c] = 0;

    for (int kt = 0; kt < NITER; ++kt) {
        const int st = kt % STAGES;
        CP_WAIT(STAGES - 2);
        __syncthreads();

        // issue loads for kt+STAGES-1 (into the stage consumed at kt-1)
        if (kt + STAGES - 1 < NITER) load_stage(kt + STAGES - 1, (kt + STAGES - 1) % STAGES);
        CP_COMMIT();

        const uint32_t stb = sbase + st * STAGE_BYTES;
#pragma unroll
        for (int s2 = 0; s2 < 2; ++s2) {            // two K=32 steps per tile
            const uint32_t kxor = s2 * 32;
            uint32_t a[4][4], b[4][2];
#pragma unroll
            for (int mi = 0; mi < 4; ++mi)
                LDSM_X4(a[mi][0], a[mi][1], a[mi][2], a[mi][3], stb + (aoff[mi] ^ kxor));
#pragma unroll
            for (int ni = 0; ni < 4; ++ni)
                LDSM_X2(b[ni][0], b[ni][1], stb + (boff[ni] ^ kxor));
#pragma unroll
            for (int mi = 0; mi < 4; ++mi)
#pragma unroll
                for (int ni = 0; ni < 4; ++ni)
                    mma_s8(acc[mi][ni], a[mi], b[ni]);
        }
    }

    // epilogue: s32 -> f32 + bias, direct coalesced-ish float2 stores
    const int g = l >> 2, tg = l & 3;
#pragma unroll
    for (int ni = 0; ni < 4; ++ni) {
        const int c = n0 + warp_n + ni * 8 + 2 * tg;
        const float bx = __ldg(bias + c), by = __ldg(bias + c + 1);
#pragma unroll
        for (int mi = 0; mi < 4; ++mi) {
            const int r = m0 + warp_m + mi * 16 + g;
            float2 o0 = make_float2((float)acc[mi][ni][0] + bx, (float)acc[mi][ni][1] + by);
            float2 o1 = make_float2((float)acc[mi][ni][2] + bx, (float)acc[mi][ni][3] + by);
            *reinterpret_cast<float2*>(out + (size_t)r * DIM_N + c) = o0;
            *reinterpret_cast<float2*>(out + (size_t)(r + 8) * DIM_N + c) = o1;
        }
    }
}

// ---------------- launch ----------------

extern "C" void kernel_launch(void* const* d_in, const int* in_sizes, int n_in,
                              void* d_out, int out_size) {
    const float* x    = (const float*)d_in[0];   // [8192, 2048]
    const float* W    = (const float*)d_in[1];   // [2048, 2048]
    const float* bias = (const float*)d_in[2];   // [2048]
    float* out = (float*)d_out;                  // [8192, 2048]

    cudaFuncSetAttribute(gemm_kernel, cudaFuncAttributeMaxDynamicSharedMemorySize, SMEM_TOTAL);

    convert_x_kernel<<<(DIM_M * DIM_K / 4) / 256, 256>>>(x);
    convert_w_kernel<<<dim3(DIM_N / 32, DIM_K / 32), dim3(32, 8)>>>(W);
    gemm_kernel<<<dim3(DIM_N / BN, DIM_M / BM), 256, SMEM_TOTAL>>>(bias, out);
}

// round 4
// speedup vs baseline: 1.0043x; 1.0043x over previous
#include <cuda_runtime.h>
#include <cstdint>

// ============================================================
// BinaryDense: out[M,N] = sign(x)[M,K] @ sign(W)[K,N] + bias[N]
// M=8192, K=2048, N=2048, fp32 in/out.
// int8 +-1 operands, mma.sync.m16n8k32.s8, s32 accum (exact).
// R4: anti-spill restructure -- 512 thr, 32x32 warp tile.
// ============================================================

#define DIM_M 8192
#define DIM_K 2048
#define DIM_N 2048

static constexpr int BM = 128;
static constexpr int BN = 128;
static constexpr int BK = 64;               // 64B rows in smem
static constexpr int STAGES = 4;
static constexpr int NITER = DIM_K / BK;    // 32
static constexpr int STAGE_BYTES = (BM + BN) * BK;      // 16384
static constexpr int SMEM_TOTAL = STAGES * STAGE_BYTES; // 65536

__device__ int8_t g_Xb[(size_t)DIM_M * DIM_K];   // 16MB, [m][k]
__device__ int8_t g_Wt[(size_t)DIM_N * DIM_K];   // 4MB,  [n][k]

// ---------------- helpers ----------------

__device__ __forceinline__ uint32_t smem_u32(const void* p) {
    uint32_t a;
    asm("{ .reg .u64 t; cvta.to.shared.u64 t, %1; cvt.u32.u64 %0, t; }" : "=r"(a) : "l"(p));
    return a;
}

__device__ __forceinline__ constexpr int swz(int r) {
    // permute the 4 16B-chunks of a 64B row; any 8 consecutive rows cover
    // 8 distinct 16B bank-groups -> conflict-free ldmatrix (verified R3)
    return (r & 3) ^ ((r >> 2) & 1);
}

__device__ __forceinline__ void cp_async16(uint32_t dst, const void* src) {
    asm volatile("cp.async.cg.shared.global [%0], [%1], 16;" :: "r"(dst), "l"(src));
}

#define CP_COMMIT() asm volatile("cp.async.commit_group;" ::: "memory")
#define CP_WAIT(n)  asm volatile("cp.async.wait_group %0;" :: "n"(n) : "memory")

#define LDSM_X4(r0, r1, r2, r3, addr) \
    asm volatile("ldmatrix.sync.aligned.m8n8.x4.shared.b16 {%0,%1,%2,%3}, [%4];" \
                 : "=r"(r0), "=r"(r1), "=r"(r2), "=r"(r3) : "r"(addr))

__device__ __forceinline__ void mma_s8(int* d, const uint32_t* a, const uint32_t* b) {
    asm volatile(
        "mma.sync.aligned.m16n8k32.row.col.s32.s8.s8.s32 "
        "{%0,%1,%2,%3}, {%4,%5,%6,%7}, {%8,%9}, {%0,%1,%2,%3};"
        : "+r"(d[0]), "+r"(d[1]), "+r"(d[2]), "+r"(d[3])
        : "r"(a[0]), "r"(a[1]), "r"(a[2]), "r"(a[3]), "r"(b[0]), "r"(b[1]));
}

// ---------------- conversion kernels ----------------

__global__ void convert_x_kernel(const float* __restrict__ x) {
    size_t i = (size_t)blockIdx.x * blockDim.x + threadIdx.x;  // one float4
    float4 v = reinterpret_cast<const float4*>(x)[i];
    uint32_t p = (v.x < 0.0f ? 0xFFu : 0x01u)
               | ((v.y < 0.0f ? 0xFFu : 0x01u) << 8)
               | ((v.z < 0.0f ? 0xFFu : 0x01u) << 16)
               | ((v.w < 0.0f ? 0xFFu : 0x01u) << 24);
    reinterpret_cast<uint32_t*>(g_Xb)[i] = p;
}

__global__ void convert_w_kernel(const float* __restrict__ W) {
    __shared__ float t[32][33];
    int n0 = blockIdx.x * 32, k0 = blockIdx.y * 32;
    int tx = threadIdx.x, ty = threadIdx.y;   // blockDim (32, 8)
#pragma unroll
    for (int j = 0; j < 32; j += 8)
        t[ty + j][tx] = W[(size_t)(k0 + ty + j) * DIM_N + n0 + tx];
    __syncthreads();
#pragma unroll
    for (int j = 0; j < 32; j += 8) {
        float v = t[tx][ty + j];   // = W[k0+tx][n0+ty+j]
        g_Wt[(size_t)(n0 + ty + j) * DIM_K + k0 + tx] = (v < 0.0f) ? (int8_t)-1 : (int8_t)1;
    }
}

// ---------------- GEMM kernel ----------------

__global__ void __launch_bounds__(512, 1)
gemm_kernel(const float* __restrict__ bias, float* __restrict__ out) {
    extern __shared__ char smem[];
    const uint32_t sbase = smem_u32(smem);
    const int tid = threadIdx.x;
    const int w = tid >> 5, l = tid & 31;
    const int m0 = blockIdx.y * BM;
    const int n0 = blockIdx.x * BN;
    const int warp_m = (w >> 2) * 32;   // 4x4 warp grid: 32x32 per warp
    const int warp_n = (w & 3) * 32;

    const int8_t* Xp = g_Xb + (size_t)m0 * DIM_K;
    const int8_t* Wp = g_Wt + (size_t)n0 * DIM_K;

    // ldmatrix lane addresses (k-step 0; k-step 1 = addr ^ 32)
    // A: two x4 loads (m16 tiles mi=0,1), lanes 0-15 rows, 16-31 k-hi chunk
    uint32_t aoff[2];
#pragma unroll
    for (int mi = 0; mi < 2; ++mi) {
        int r  = warp_m + mi * 16 + (l & 15);
        int c4 = (l >> 4);
        aoff[mi] = (uint32_t)(r * 64 + ((c4 ^ swz(r)) << 4));
    }
    // B: two x4 loads, each covering two n8 tiles x two k-chunks
    //   lanes 0-7: (nt)k-lo, 8-15: (nt)k-hi, 16-23: (nt+1)k-lo, 24-31: (nt+1)k-hi
    uint32_t boff[2];
#pragma unroll
    for (int p = 0; p < 2; ++p) {
        int nt = p * 2 + ((l >> 4) & 1);          // which n8 tile pair member
        int r  = warp_n + nt * 8 + (l & 7);
        int c4 = (l >> 3) & 1;
        boff[p] = (uint32_t)(BM * BK + r * 64 + ((c4 ^ swz(r)) << 4));
    }

    // cp.async: 512 threads, 1 A chunk + 1 B chunk each
    const int ld_c4 = tid & 3;
    const int ld_r  = tid >> 2;   // 0..127

    auto load_stage = [&](int kt, int st) {
        const uint32_t ab = sbase + st * STAGE_BYTES;
        const int kb = kt * BK;
        cp_async16(ab + ld_r * 64 + ((ld_c4 ^ swz(ld_r)) << 4),
                   Xp + (size_t)ld_r * DIM_K + kb + ld_c4 * 16);
        cp_async16(ab + BM * BK + ld_r * 64 + ((ld_c4 ^ swz(ld_r)) << 4),
                   Wp + (size_t)ld_r * DIM_K + kb + ld_c4 * 16);
    };

#pragma unroll
    for (int s = 0; s < STAGES - 1; ++s) { load_stage(s, s); CP_COMMIT(); }

    int acc[2][4][4];
#pragma unroll
    for (int mi = 0; mi < 2; ++mi)
#pragma unroll
        for (int ni = 0; ni < 4; ++ni)
#pragma unroll
            for (int c = 0; c < 4; ++c) acc[mi][ni][c] = 0;

    for (int kt = 0; kt < NITER; ++kt) {
        const int st = kt % STAGES;
        CP_WAIT(STAGES - 2);
        __syncthreads();

        if (kt + STAGES - 1 < NITER) load_stage(kt + STAGES - 1, (kt + STAGES - 1) % STAGES);
        CP_COMMIT();

        const uint32_t stb = sbase + st * STAGE_BYTES;
#pragma unroll
        for (int s2 = 0; s2 < 2; ++s2) {          // two K=32 steps per BK=64 tile
            const uint32_t kxor = s2 * 32;
            uint32_t a[2][4], b[4][2];
#pragma unroll
            for (int mi = 0; mi < 2; ++mi)
                LDSM_X4(a[mi][0], a[mi][1], a[mi][2], a[mi][3], stb + (aoff[mi] ^ kxor));
#pragma unroll
            for (int p = 0; p < 2; ++p) {
                uint32_t r0, r1, r2, r3;
                LDSM_X4(r0, r1, r2, r3, stb + (boff[p] ^ kxor));
                b[p * 2 + 0][0] = r0; b[p * 2 + 0][1] = r1;
                b[p * 2 + 1][0] = r2; b[p * 2 + 1][1] = r3;
            }
#pragma unroll
            for (int mi = 0; mi < 2; ++mi)
#pragma unroll
                for (int ni = 0; ni < 4; ++ni)
                    mma_s8(acc[mi][ni], a[mi], b[ni]);
        }
    }

    // epilogue: s32 -> f32 + bias, float2 stores
    const int g = l >> 2, tg = l & 3;
#pragma unroll
    for (int ni = 0; ni < 4; ++ni) {
        const int c = n0 + warp_n + ni * 8 + 2 * tg;
        const float bx = __ldg(bias + c), by = __ldg(bias + c + 1);
#pragma unroll
        for (int mi = 0; mi < 2; ++mi) {
            const int r = m0 + warp_m + mi * 16 + g;
            float2 o0 = make_float2((float)acc[mi][ni][0] + bx, (float)acc[mi][ni][1] + by);
            float2 o1 = make_float2((float)acc[mi][ni][2] + bx, (float)acc[mi][ni][3] + by);
            *reinterpret_cast<float2*>(out + (size_t)r * DIM_N + c) = o0;
            *reinterpret_cast<float2*>(out + (size_t)(r + 8) * DIM_N + c) = o1;
        }
    }
}

// ---------------- launch ----------------

extern "C" void kernel_launch(void* const* d_in, const int* in_sizes, int n_in,
                              void* d_out, int out_size) {
    const float* x    = (const float*)d_in[0];   // [8192, 2048]
    const float* W    = (const float*)d_in[1];   // [2048, 2048]
    const float* bias = (const float*)d_in[2];   // [2048]
    float* out = (float*)d_out;                  // [8192, 2048]

    cudaFuncSetAttribute(gemm_kernel, cudaFuncAttributeMaxDynamicSharedMemorySize, SMEM_TOTAL);

    convert_x_kernel<<<(DIM_M * DIM_K / 4) / 256, 256>>>(x);
    convert_w_kernel<<<dim3(DIM_N / 32, DIM_K / 32), dim3(32, 8)>>>(W);
    gemm_kernel<<<dim3(DIM_N / BN, DIM_M / BM), 512, SMEM_TOTAL>>>(bias, out);
}

// round 7
// speedup vs baseline: 1.7705x; 1.7630x over previous
#include <cuda_runtime.h>
#include <cstdint>

// ============================================================
// BinaryDense: out[M,N] = sign(x)[M,K] @ sign(W)[K,N] + bias[N]
// M=8192, K=2048, N=2048, fp32 in/out.
// R5: XNOR-popcount path. Legacy mma.sync on sm_103a measured
// ~58 cyc/inst/SMSP (de-rated ~15x; tcgen05 is ptxas-gated off
// in this harness), so the ALU pipe wins:
//   out = K - 2*popc(xbits ^ wbits) + bias
// ============================================================

#define DIM_M 8192
#define DIM_K 2048
#define DIM_N 2048
#define KW    (DIM_K / 32)        // 64 words per row

static constexpr int BM = 128;
static constexpr int BN = 64;
static constexpr int RSTRIDE = 68;      // words; odd 16B-unit stride -> min bank conflicts
static constexpr int SMEM_WORDS = (BM + BN) * RSTRIDE;     // 13056
static constexpr int SMEM_TOTAL = SMEM_WORDS * 4;          // 52224 B

// packed sign bits (bit=1 <-> negative)
__device__ uint32_t g_Xp[(size_t)DIM_M * KW];   // 2MB
__device__ uint32_t g_Wp[(size_t)DIM_N * KW];   // 0.5MB

// ---------------- helpers ----------------

__device__ __forceinline__ uint32_t smem_u32(const void* p) {
    uint32_t a;
    asm("{ .reg .u64 t; cvta.to.shared.u64 t, %1; cvt.u32.u64 %0, t; }" : "=r"(a) : "l"(p));
    return a;
}

__device__ __forceinline__ void cp_async16(uint32_t dst, const void* src) {
    asm volatile("cp.async.cg.shared.global [%0], [%1], 16;" :: "r"(dst), "l"(src));
}
#define CP_COMMIT() asm volatile("cp.async.commit_group;" ::: "memory")
#define CP_WAIT0()  asm volatile("cp.async.wait_group 0;" ::: "memory")

// ---------------- profiling-alignment dummy ----------------
__global__ void dummy_kernel() {}

// ---------------- conversion kernels ----------------

// x fp32 -> packed sign bits via ballot. Each block: 8192 consecutive floats.
__global__ void convert_x_kernel(const float* __restrict__ x) {
    const int tid = threadIdx.x;                    // 256 thr, 8 warps
    const int lane = tid & 31, warp = tid >> 5;
    const size_t base = (size_t)blockIdx.x * 8192;
#pragma unroll
    for (int i = 0; i < 32; ++i) {
        float v = x[base + (size_t)i * 256 + tid];
        uint32_t word = __ballot_sync(0xFFFFFFFFu, v < 0.0f);
        if (lane == 0) g_Xp[(base >> 5) + i * 8 + warp] = word;
    }
}

// W[k][n] -> Wp[n][kw] packed bits (transpose via smem tile + ballot)
__global__ void convert_w_kernel(const float* __restrict__ W) {
    __shared__ float t[32][33];
    const int n0 = blockIdx.x * 32, k0 = blockIdx.y * 32;
    const int tx = threadIdx.x, ty = threadIdx.y;   // blockDim (32, 8)
#pragma unroll
    for (int j = 0; j < 32; j += 8)
        t[ty + j][tx] = W[(size_t)(k0 + ty + j) * DIM_N + n0 + tx];
    __syncthreads();
    // warp w handles n-local {4w .. 4w+3}; lane = k index within tile
    const int lane = tx, w = ty;
#pragma unroll
    for (int j = 0; j < 4; ++j) {
        int nl = w * 4 + j;
        uint32_t word = __ballot_sync(0xFFFFFFFFu, t[lane][nl] < 0.0f);
        if (lane == 0) g_Wp[(size_t)(n0 + nl) * KW + (k0 >> 5)] = word;
    }
}

// ---------------- popcount GEMM ----------------

__global__ void __launch_bounds__(256)
gemm_kernel(const float* __restrict__ bias, float* __restrict__ out) {
    extern __shared__ uint32_t smem[];
    uint32_t* As = smem;                   // [BM][RSTRIDE]
    uint32_t* Bs = smem + BM * RSTRIDE;    // [BN][RSTRIDE]
    const uint32_t sbase = smem_u32(smem);

    const int tid = threadIdx.x;
    const int m0 = blockIdx.y * BM;
    const int n0 = blockIdx.x * BN;
    const int m_t = tid >> 4;      // 0..15 ; thread rows: m_t + mi*16
    const int n_t = tid & 15;      // 0..15 ; thread cols: n_t + ni*16

    // ---- load tiles (full K), 16B chunks ----
    {
        const char* Xsrc = reinterpret_cast<const char*>(g_Xp) + (size_t)m0 * (KW * 4);
        const char* Wsrc = reinterpret_cast<const char*>(g_Wp) + (size_t)n0 * (KW * 4);
        const uint32_t abase = sbase;
        const uint32_t bbase = sbase + BM * RSTRIDE * 4;
#pragma unroll
        for (int i = 0; i < 8; ++i) {              // A: 2048 chunks / 256 thr
            int task = tid + i * 256;
            int r = task >> 4, c = task & 15;
            cp_async16(abase + (r * RSTRIDE + c * 4) * 4, Xsrc + (size_t)r * 256 + c * 16);
        }
#pragma unroll
        for (int i = 0; i < 4; ++i) {              // B: 1024 chunks / 256 thr
            int task = tid + i * 256;
            int r = task >> 4, c = task & 15;
            cp_async16(bbase + (r * RSTRIDE + c * 4) * 4, Wsrc + (size_t)r * 256 + c * 16);
        }
        CP_COMMIT();
        CP_WAIT0();
        __syncthreads();
    }

    // ---- compute: acc[mi][ni] = # mismatching bits ----
    int acc[8][4];
#pragma unroll
    for (int mi = 0; mi < 8; ++mi)
#pragma unroll
        for (int ni = 0; ni < 4; ++ni) acc[mi][ni] = 0;

#pragma unroll 2
    for (int kq = 0; kq < KW / 4; ++kq) {          // 16 uint4 groups
        uint4 b4[4];
#pragma unroll
        for (int ni = 0; ni < 4; ++ni)
            b4[ni] = *reinterpret_cast<const uint4*>(Bs + (n_t + ni * 16) * RSTRIDE + kq * 4);
#pragma unroll
        for (int mi = 0; mi < 8; ++mi) {
            const uint4 a = *reinterpret_cast<const uint4*>(As + (m_t + mi * 16) * RSTRIDE + kq * 4);
#pragma unroll
            for (int ni = 0; ni < 4; ++ni) {
                acc[mi][ni] += __popc(a.x ^ b4[ni].x) + __popc(a.y ^ b4[ni].y)
                             + __popc(a.z ^ b4[ni].z) + __popc(a.w ^ b4[ni].w);
            }
        }
    }

    // ---- epilogue: out = K - 2*mismatch + bias ----
    float bn[4];
#pragma unroll
    for (int ni = 0; ni < 4; ++ni) bn[ni] = __ldg(bias + n0 + n_t + ni * 16);

#pragma unroll
    for (int mi = 0; mi < 8; ++mi) {
        const size_t row = (size_t)(m0 + m_t + mi * 16) * DIM_N + n0;
#pragma unroll
        for (int ni = 0; ni < 4; ++ni) {
            out[row + n_t + ni * 16] = (float)(DIM_K - 2 * acc[mi][ni]) + bn[ni];
        }
    }
}

// ---------------- launch ----------------

extern "C" void kernel_launch(void* const* d_in, const int* in_sizes, int n_in,
                              void* d_out, int out_size) {
    const float* x    = (const float*)d_in[0];   // [8192, 2048]
    const float* W    = (const float*)d_in[1];   // [2048, 2048]
    const float* bias = (const float*)d_in[2];   // [2048]
    float* out = (float*)d_out;                  // [8192, 2048]

    cudaFuncSetAttribute(gemm_kernel, cudaFuncAttributeMaxDynamicSharedMemorySize, SMEM_TOTAL);

    dummy_kernel<<<1, 32>>>();   // aligns ncu capture slot onto gemm_kernel
    convert_x_kernel<<<(DIM_M * DIM_K) / 8192, 256>>>(x);
    convert_w_kernel<<<dim3(DIM_N / 32, DIM_K / 32), dim3(32, 8)>>>(W);
    gemm_kernel<<<dim3(DIM_N / BN, DIM_M / BM), 256, SMEM_TOTAL>>>(bias, out);
}

// round 8
// speedup vs baseline: 1.9073x; 1.0773x over previous
#include <cuda_runtime.h>
#include <cstdint>

// ============================================================
// BinaryDense: out[M,N] = sign(x)[M,K] @ sign(W)[K,N] + bias[N]
// M=8192, K=2048, N=2048, fp32 in/out.
// XNOR-popcount path (tensor pipes unusable: tcgen05 ptxas-gated,
// legacy mma.sync de-rated ~58cyc/inst).
// R7: occupancy fix -- cap regs to 128 (2 CTAs/SM, 16 warps),
// kq loop unroll 1 to keep live set ~70 regs (was 137 -> 1 CTA).
// ============================================================

#define DIM_M 8192
#define DIM_K 2048
#define DIM_N 2048
#define KW    (DIM_K / 32)        // 64 words per row

static constexpr int BM = 128;
static constexpr int BN = 64;
static constexpr int RSTRIDE = 68;      // words; odd 16B-unit stride -> min bank conflicts
static constexpr int SMEM_WORDS = (BM + BN) * RSTRIDE;     // 13056
static constexpr int SMEM_TOTAL = SMEM_WORDS * 4;          // 52224 B (x2 CTAs = 104KB/SM)

// packed sign bits (bit=1 <-> negative)
__device__ uint32_t g_Xp[(size_t)DIM_M * KW];   // 2MB
__device__ uint32_t g_Wp[(size_t)DIM_N * KW];   // 0.5MB

// ---------------- helpers ----------------

__device__ __forceinline__ uint32_t smem_u32(const void* p) {
    uint32_t a;
    asm("{ .reg .u64 t; cvta.to.shared.u64 t, %1; cvt.u32.u64 %0, t; }" : "=r"(a) : "l"(p));
    return a;
}

__device__ __forceinline__ void cp_async16(uint32_t dst, const void* src) {
    asm volatile("cp.async.cg.shared.global [%0], [%1], 16;" :: "r"(dst), "l"(src));
}
#define CP_COMMIT() asm volatile("cp.async.commit_group;" ::: "memory")
#define CP_WAIT0()  asm volatile("cp.async.wait_group 0;" ::: "memory")

// ---------------- profiling-alignment dummy ----------------
__global__ void dummy_kernel() {}

// ---------------- conversion kernels ----------------

// x fp32 -> packed sign bits via ballot. Each block: 8192 consecutive floats.
__global__ void convert_x_kernel(const float* __restrict__ x) {
    const int tid = threadIdx.x;                    // 256 thr, 8 warps
    const int lane = tid & 31, warp = tid >> 5;
    const size_t base = (size_t)blockIdx.x * 8192;
#pragma unroll
    for (int i = 0; i < 32; ++i) {
        float v = x[base + (size_t)i * 256 + tid];
        uint32_t word = __ballot_sync(0xFFFFFFFFu, v < 0.0f);
        if (lane == 0) g_Xp[(base >> 5) + i * 8 + warp] = word;
    }
}

// W[k][n] -> Wp[n][kw] packed bits (transpose via smem tile + ballot)
__global__ void convert_w_kernel(const float* __restrict__ W) {
    __shared__ float t[32][33];
    const int n0 = blockIdx.x * 32, k0 = blockIdx.y * 32;
    const int tx = threadIdx.x, ty = threadIdx.y;   // blockDim (32, 8)
#pragma unroll
    for (int j = 0; j < 32; j += 8)
        t[ty + j][tx] = W[(size_t)(k0 + ty + j) * DIM_N + n0 + tx];
    __syncthreads();
    const int lane = tx, w = ty;
#pragma unroll
    for (int j = 0; j < 4; ++j) {
        int nl = w * 4 + j;
        uint32_t word = __ballot_sync(0xFFFFFFFFu, t[lane][nl] < 0.0f);
        if (lane == 0) g_Wp[(size_t)(n0 + nl) * KW + (k0 >> 5)] = word;
    }
}

// ---------------- popcount GEMM ----------------

__global__ void __launch_bounds__(256, 2)
gemm_kernel(const float* __restrict__ bias, float* __restrict__ out) {
    extern __shared__ uint32_t smem[];
    uint32_t* As = smem;                   // [BM][RSTRIDE]
    uint32_t* Bs = smem + BM * RSTRIDE;    // [BN][RSTRIDE]
    const uint32_t sbase = smem_u32(smem);

    const int tid = threadIdx.x;
    const int m0 = blockIdx.y * BM;
    const int n0 = blockIdx.x * BN;
    const int m_t = tid >> 4;      // 0..15 ; thread rows: m_t + mi*16
    const int n_t = tid & 15;      // 0..15 ; thread cols: n_t + ni*16

    // ---- load tiles (full K), 16B chunks ----
    {
        const char* Xsrc = reinterpret_cast<const char*>(g_Xp) + (size_t)m0 * (KW * 4);
        const char* Wsrc = reinterpret_cast<const char*>(g_Wp) + (size_t)n0 * (KW * 4);
        const uint32_t abase = sbase;
        const uint32_t bbase = sbase + BM * RSTRIDE * 4;
#pragma unroll
        for (int i = 0; i < 8; ++i) {              // A: 2048 chunks / 256 thr
            int task = tid + i * 256;
            int r = task >> 4, c = task & 15;
            cp_async16(abase + (r * RSTRIDE + c * 4) * 4, Xsrc + (size_t)r * 256 + c * 16);
        }
#pragma unroll
        for (int i = 0; i < 4; ++i) {              // B: 1024 chunks / 256 thr
            int task = tid + i * 256;
            int r = task >> 4, c = task & 15;
            cp_async16(bbase + (r * RSTRIDE + c * 4) * 4, Wsrc + (size_t)r * 256 + c * 16);
        }
        CP_COMMIT();
        CP_WAIT0();
        __syncthreads();
    }

    // ---- compute: acc[mi][ni] = # mismatching bits ----
    int acc[8][4];
#pragma unroll
    for (int mi = 0; mi < 8; ++mi)
#pragma unroll
        for (int ni = 0; ni < 4; ++ni) acc[mi][ni] = 0;

#pragma unroll 1
    for (int kq = 0; kq < KW / 4; ++kq) {          // 16 uint4 groups
        uint4 b4[4];
#pragma unroll
        for (int ni = 0; ni < 4; ++ni)
            b4[ni] = *reinterpret_cast<const uint4*>(Bs + (n_t + ni * 16) * RSTRIDE + kq * 4);
#pragma unroll
        for (int mi = 0; mi < 8; ++mi) {
            const uint4 a = *reinterpret_cast<const uint4*>(As + (m_t + mi * 16) * RSTRIDE + kq * 4);
#pragma unroll
            for (int ni = 0; ni < 4; ++ni) {
                acc[mi][ni] += __popc(a.x ^ b4[ni].x) + __popc(a.y ^ b4[ni].y)
                             + __popc(a.z ^ b4[ni].z) + __popc(a.w ^ b4[ni].w);
            }
        }
    }

    // ---- epilogue: out = K - 2*mismatch + bias ----
    float bn[4];
#pragma unroll
    for (int ni = 0; ni < 4; ++ni) bn[ni] = __ldg(bias + n0 + n_t + ni * 16);

#pragma unroll
    for (int mi = 0; mi < 8; ++mi) {
        const size_t row = (size_t)(m0 + m_t + mi * 16) * DIM_N + n0;
#pragma unroll
        for (int ni = 0; ni < 4; ++ni) {
            out[row + n_t + ni * 16] = (float)(DIM_K - 2 * acc[mi][ni]) + bn[ni];
        }
    }
}

// ---------------- launch ----------------

extern "C" void kernel_launch(void* const* d_in, const int* in_sizes, int n_in,
                              void* d_out, int out_size) {
    const float* x    = (const float*)d_in[0];   // [8192, 2048]
    const float* W    = (const float*)d_in[1];   // [2048, 2048]
    const float* bias = (const float*)d_in[2];   // [2048]
    float* out = (float*)d_out;                  // [8192, 2048]

    cudaFuncSetAttribute(gemm_kernel, cudaFuncAttributeMaxDynamicSharedMemorySize, SMEM_TOTAL);

    dummy_kernel<<<1, 32>>>();   // aligns ncu capture slot onto gemm_kernel
    convert_x_kernel<<<(DIM_M * DIM_K) / 8192, 256>>>(x);
    convert_w_kernel<<<dim3(DIM_N / 32, DIM_K / 32), dim3(32, 8)>>>(W);
    gemm_kernel<<<dim3(DIM_N / BN, DIM_M / BM), 256, SMEM_TOTAL>>>(bias, out);
}

// round 11
// speedup vs baseline: 2.0433x; 1.0713x over previous
#include <cuda_runtime.h>
#include <cstdint>

// ============================================================
// BinaryDense: out = sign(x) @ sign(W) + bias ; M=8192,K=2048,N=2048
// R9: hybrid pipes. alu pipe is the popc-path's hard ceiling
// (issue pinned ~34% indep. of occupancy), so split K:
//   warps 0-7 : XNOR+POPC over K[0,1280)   (bit operands, alu pipe)
//   warps 8-15: mma.sync s8 over K[1280,2048) (byte operands, IMMA pipe)
// Same 128x64 output tile per CTA; partials combined via smem.
// ============================================================

#define DIM_M 8192
#define DIM_K 2048
#define DIM_N 2048
#define KW    64                  // bit-words per row, full K

static constexpr int BM = 128;
static constexpr int BN = 64;
static constexpr int KP   = 1280;           // popc K range
static constexpr int KPW  = KP / 32;        // 40 words
static constexpr int KQ   = KPW / 4;        // 10 uint4 groups
static constexpr int KMMA = DIM_K - KP;     // 768
static constexpr int NKT  = KMMA / 64;      // 12 chunks of 64B
static constexpr int RST  = 44;             // popc row stride (words): 11 16B-units (odd)

// smem (bytes)
static constexpr int OFF_AP   = 0;                          // 128*44*4 = 22528
static constexpr int OFF_BP   = 128 * RST * 4;              // 22528
static constexpr int OFF_MMA  = OFF_BP + 64 * RST * 4;      // 33792
static constexpr int STG_B    = 128 * 64 + 64 * 64;         // 12288 (A=8K,B=4K)
static constexpr int NSTAGE   = 3;
static constexpr int OFF_ACC  = OFF_MMA;                    // epilogue overlay (128*66*4=33792 <= 36864)
static constexpr int SMEM_TOTAL = OFF_MMA + NSTAGE * STG_B; // 70656

// scratch (no allocations allowed)
__device__ uint32_t g_Xp[(size_t)DIM_M * KW];        // bit-packed x, 2MB
__device__ uint32_t g_Wp[(size_t)DIM_N * KW];        // bit-packed W^T, 0.5MB
__device__ int8_t   g_Xb2[(size_t)DIM_M * KMMA];     // byte x, K tail, 6MB
__device__ int8_t   g_Wt2[(size_t)DIM_N * KMMA];     // byte W^T, K tail, 1.5MB

// ---------------- helpers ----------------

__device__ __forceinline__ uint32_t smem_u32(const void* p) {
    uint32_t a;
    asm("{ .reg .u64 t; cvta.to.shared.u64 t, %1; cvt.u32.u64 %0, t; }" : "=r"(a) : "l"(p));
    return a;
}
__device__ __forceinline__ constexpr int swz(int r) {   // R4-verified 16B-chunk permute
    return (r & 3) ^ ((r >> 2) & 1);
}
__device__ __forceinline__ void cp_async16(uint32_t dst, const void* src) {
    asm volatile("cp.async.cg.shared.global [%0], [%1], 16;" :: "r"(dst), "l"(src));
}
#define CP_COMMIT() asm volatile("cp.async.commit_group;" ::: "memory")
#define CP_WAIT(n)  asm volatile("cp.async.wait_group %0;" :: "n"(n) : "memory")
#define NB(id, cnt) asm volatile("bar.sync %0, %1;" :: "r"(id), "r"(cnt) : "memory")

#define LDSM_X4(r0, r1, r2, r3, addr) \
    asm volatile("ldmatrix.sync.aligned.m8n8.x4.shared.b16 {%0,%1,%2,%3}, [%4];" \
                 : "=r"(r0), "=r"(r1), "=r"(r2), "=r"(r3) : "r"(addr))

__device__ __forceinline__ void mma_s8(int* d, const uint32_t* a, const uint32_t* b) {
    asm volatile(
        "mma.sync.aligned.m16n8k32.row.col.s32.s8.s8.s32 "
        "{%0,%1,%2,%3}, {%4,%5,%6,%7}, {%8,%9}, {%0,%1,%2,%3};"
        : "+r"(d[0]), "+r"(d[1]), "+r"(d[2]), "+r"(d[3])
        : "r"(a[0]), "r"(a[1]), "r"(a[2]), "r"(a[3]), "r"(b[0]), "r"(b[1]));
}

// ---------------- profiling-alignment dummy ----------------
__global__ void dummy_kernel() {}

// ---------------- conversion kernels ----------------

// x -> bits (all K) + bytes (K tail). Block covers 8192 consecutive floats (4 rows).
__global__ void convert_x_kernel(const float* __restrict__ x) {
    const int tid = threadIdx.x;                 // 256 thr
    const int lane = tid & 31, warp = tid >> 5;
    const size_t base = (size_t)blockIdx.x * 8192;
#pragma unroll
    for (int i = 0; i < 32; ++i) {
        const size_t idx = base + (size_t)i * 256 + tid;
        float v = x[idx];
        bool neg = v < 0.0f;
        uint32_t word = __ballot_sync(0xFFFFFFFFu, neg);
        if (lane == 0) g_Xp[(base >> 5) + i * 8 + warp] = word;
        const int k = (int)(idx & (DIM_K - 1));
        if (k >= KP) {
            const size_t row = idx >> 11;
            g_Xb2[row * KMMA + (k - KP)] = neg ? (int8_t)-1 : (int8_t)1;
        }
    }
}

// W[k][n] -> Wp bits [n][kw] + Wt2 bytes [n][k-KP]
__global__ void convert_w_kernel(const float* __restrict__ W) {
    __shared__ float t[32][33];
    const int n0 = blockIdx.x * 32, k0 = blockIdx.y * 32;
    const int tx = threadIdx.x, ty = threadIdx.y;   // (32, 8)
#pragma unroll
    for (int j = 0; j < 32; j += 8)
        t[ty + j][tx] = W[(size_t)(k0 + ty + j) * DIM_N + n0 + tx];
    __syncthreads();
    const int lane = tx, w = ty;
#pragma unroll
    for (int j = 0; j < 4; ++j) {
        int nl = w * 4 + j;
        bool neg = t[lane][nl] < 0.0f;
        uint32_t word = __ballot_sync(0xFFFFFFFFu, neg);
        if (lane == 0) g_Wp[(size_t)(n0 + nl) * KW + (k0 >> 5)] = word;
        if (k0 >= KP)
            g_Wt2[(size_t)(n0 + nl) * KMMA + (k0 - KP) + lane] = neg ? (int8_t)-1 : (int8_t)1;
    }
}

// ---------------- hybrid GEMM ----------------

__global__ void __launch_bounds__(512, 1)
gemm_kernel(const float* __restrict__ bias, float* __restrict__ out) {
    extern __shared__ char smem[];
    const uint32_t sbase = smem_u32(smem);
    const int tid = threadIdx.x;
    const int m0 = blockIdx.y * BM;
    const int n0 = blockIdx.x * BN;

    if (tid < 256) {
        // ================= popc half: K in [0, KP) =================
        const int m_t = tid >> 4;      // 0..15
        const int n_t = tid & 15;      // 0..15

        // load bit tiles
        for (int t = tid; t < (BM + BN) * KQ; t += 256) {
            uint32_t dst; const uint32_t* src;
            if (t < BM * KQ) {
                int r = t / KQ, c = t - r * KQ;
                dst = sbase + OFF_AP + (r * RST + c * 4) * 4;
                src = g_Xp + (size_t)(m0 + r) * KW + c * 4;
            } else {
                int u = t - BM * KQ;
                int r = u / KQ, c = u - r * KQ;
                dst = sbase + OFF_BP + (r * RST + c * 4) * 4;
                src = g_Wp + (size_t)(n0 + r) * KW + c * 4;
            }
            cp_async16(dst, src);
        }
        CP_COMMIT(); CP_WAIT(0);
        NB(1, 256);

        const uint32_t* As = reinterpret_cast<const uint32_t*>(smem + OFF_AP);
        const uint32_t* Bs = reinterpret_cast<const uint32_t*>(smem + OFF_BP);

        int acc[8][4];
#pragma unroll
        for (int mi = 0; mi < 8; ++mi)
#pragma unroll
            for (int ni = 0; ni < 4; ++ni) acc[mi][ni] = 0;

#pragma unroll 1
        for (int kq = 0; kq < KQ; ++kq) {
            uint4 b4[4];
#pragma unroll
            for (int ni = 0; ni < 4; ++ni)
                b4[ni] = *reinterpret_cast<const uint4*>(Bs + (n_t + ni * 16) * RST + kq * 4);
#pragma unroll
            for (int mi = 0; mi < 8; ++mi) {
                const uint4 a = *reinterpret_cast<const uint4*>(As + (m_t + mi * 16) * RST + kq * 4);
#pragma unroll
                for (int ni = 0; ni < 4; ++ni) {
                    acc[mi][ni] += __popc(a.x ^ b4[ni].x) + __popc(a.y ^ b4[ni].y)
                                 + __popc(a.z ^ b4[ni].z) + __popc(a.w ^ b4[ni].w);
                }
            }
        }

        NB(0, 512);   // join: mma partials now in smem

        const int* accS = reinterpret_cast<const int*>(smem + OFF_ACC);
        float bn[4];
#pragma unroll
        for (int ni = 0; ni < 4; ++ni) bn[ni] = __ldg(bias + n0 + n_t + ni * 16);
#pragma unroll
        for (int mi = 0; mi < 8; ++mi) {
            const int m = m_t + mi * 16;
            const size_t row = (size_t)(m0 + m) * DIM_N + n0;
#pragma unroll
            for (int ni = 0; ni < 4; ++ni) {
                const int n = n_t + ni * 16;
                out[row + n] = (float)(KP - 2 * acc[mi][ni] + accS[m * 66 + n]) + bn[ni];
            }
        }
    } else {
        // ================= mma half: K in [KP, 2048) =================
        const int tid2 = tid - 256;
        const int w = tid2 >> 5, l = tid2 & 31;      // w 0..7
        const int warp_m = (w >> 2) * 64;            // 2x4 warp grid: 64x16 tiles
        const int warp_n = (w & 3) * 16;

        // ldmatrix lane offsets within a stage (R4-verified; k-step1 = ^32)
        uint32_t aoff[4];
#pragma unroll
        for (int mi = 0; mi < 4; ++mi) {
            int r  = warp_m + mi * 16 + (l & 15);
            int c4 = l >> 4;
            aoff[mi] = (uint32_t)(r * 64 + ((c4 ^ swz(r)) << 4));
        }
        uint32_t boff;
        {
            int nt = (l >> 4) & 1;
            int r  = warp_n + nt * 8 + (l & 7);
            int c4 = (l >> 3) & 1;
            boff = (uint32_t)(128 * 64 + r * 64 + ((c4 ^ swz(r)) << 4));
        }

        const char* Xsrc = reinterpret_cast<const char*>(g_Xb2) + (size_t)m0 * KMMA;
        const char* Wsrc = reinterpret_cast<const char*>(g_Wt2) + (size_t)n0 * KMMA;

        auto load_stage = [&](int kt, int st) {
            const uint32_t base = sbase + OFF_MMA + st * STG_B;
            const int kb = kt * 64;
#pragma unroll
            for (int i = 0; i < 3; ++i) {
                int t = tid2 + i * 256;          // 0..767
                if (t < 512) {
                    int r = t >> 2, c = t & 3;
                    cp_async16(base + r * 64 + ((c ^ swz(r)) << 4),
                               Xsrc + (size_t)r * KMMA + kb + c * 16);
                } else {
                    int u = t - 512;
                    int r = u >> 2, c = u & 3;
                    cp_async16(base + 128 * 64 + r * 64 + ((c ^ swz(r)) << 4),
                               Wsrc + (size_t)r * KMMA + kb + c * 16);
                }
            }
        };

        load_stage(0, 0); CP_COMMIT();
        load_stage(1, 1); CP_COMMIT();

        int acc[4][2][4];
#pragma unroll
        for (int mi = 0; mi < 4; ++mi)
#pragma unroll
            for (int ni = 0; ni < 2; ++ni)
#pragma unroll
                for (int c = 0; c < 4; ++c) acc[mi][ni][c] = 0;

        for (int kt = 0; kt < NKT; ++kt) {
            CP_WAIT(1);
            NB(2, 256);
            if (kt + 2 < NKT) load_stage(kt + 2, (kt + 2) % NSTAGE);
            CP_COMMIT();

            const uint32_t stb = sbase + OFF_MMA + (kt % NSTAGE) * STG_B;
#pragma unroll
            for (int s2 = 0; s2 < 2; ++s2) {
                const uint32_t kxor = s2 * 32;
                uint32_t a[4][4], b[2][2];
#pragma unroll
                for (int mi = 0; mi < 4; ++mi)
                    LDSM_X4(a[mi][0], a[mi][1], a[mi][2], a[mi][3], stb + (aoff[mi] ^ kxor));
                {
                    uint32_t r0, r1, r2, r3;
                    LDSM_X4(r0, r1, r2, r3, stb + (boff ^ kxor));
                    b[0][0] = r0; b[0][1] = r1; b[1][0] = r2; b[1][1] = r3;
                }
#pragma unroll
                for (int mi = 0; mi < 4; ++mi)
#pragma unroll
                    for (int ni = 0; ni < 2; ++ni)
                        mma_s8(acc[mi][ni], a[mi], b[ni]);
            }
        }

        NB(2, 256);   // all mma warps done reading stages
        int* accS = reinterpret_cast<int*>(smem + OFF_ACC);
        const int g = l >> 2, tg = l & 3;
#pragma unroll
        for (int mi = 0; mi < 4; ++mi)
#pragma unroll
            for (int ni = 0; ni < 2; ++ni) {
                const int r = warp_m + mi * 16 + g;
                const int c = warp_n + ni * 8 + 2 * tg;
                accS[r * 66 + c]           = acc[mi][ni][0];
                accS[r * 66 + c + 1]       = acc[mi][ni][1];
                accS[(r + 8) * 66 + c]     = acc[mi][ni][2];
                accS[(r + 8) * 66 + c + 1] = acc[mi][ni][3];
            }

        NB(0, 512);   // join with popc half (which does the combine+store)
    }
}

// ---------------- launch ----------------

extern "C" void kernel_launch(void* const* d_in, const int* in_sizes, int n_in,
                              void* d_out, int out_size) {
    const float* x    = (const float*)d_in[0];   // [8192, 2048]
    const float* W    = (const float*)d_in[1];   // [2048, 2048]
    const float* bias = (const float*)d_in[2];   // [2048]
    float* out = (float*)d_out;                  // [8192, 2048]

    cudaFuncSetAttribute(gemm_kernel, cudaFuncAttributeMaxDynamicSharedMemorySize, SMEM_TOTAL);

    dummy_kernel<<<1, 32>>>();   // keeps ncu capture slot on gemm_kernel
    convert_x_kernel<<<(DIM_M * DIM_K) / 8192, 256>>>(x);
    convert_w_kernel<<<dim3(DIM_N / 32, DIM_K / 32), dim3(32, 8)>>>(W);
    gemm_kernel<<<dim3(DIM_N / BN, DIM_M / BM), 512, SMEM_TOTAL>>>(bias, out);
}

// round 12
// speedup vs baseline: 2.1726x; 1.0633x over previous
#include <cuda_runtime.h>
#include <cstdint>

// ============================================================
// BinaryDense: out = sign(x) @ sign(W) + bias ; M=8192,K=2048,N=2048
// Hybrid pipes (R9), rebalanced (R12):
//   warps 0-7 : XNOR+POPC over K[0,1408)   (bit operands, alu pipe)
//   warps 8-15: mma.sync s8 over K[1408,2048) (byte operands, IMMA pipe)
// Balance from measured rates: popc 8.86 K/us, mma 4.49 K/us -> f*=0.664.
// ============================================================

#define DIM_M 8192
#define DIM_K 2048
#define DIM_N 2048
#define KW    64                  // bit-words per row, full K

static constexpr int BM = 128;
static constexpr int BN = 64;
static constexpr int KP   = 1408;           // popc K range (f = 0.6875)
static constexpr int KPW  = KP / 32;        // 44 words
static constexpr int KQ   = KPW / 4;        // 11 uint4 groups
static constexpr int KMMA = DIM_K - KP;     // 640
static constexpr int NKT  = KMMA / 64;      // 10 chunks of 64B
static constexpr int RST  = 44;             // popc row stride (words) = 11 16B-units (odd)

// smem (bytes)
static constexpr int OFF_AP   = 0;                          // 128*44*4 = 22528
static constexpr int OFF_BP   = 128 * RST * 4;              // +64*44*4 = 11264
static constexpr int OFF_MMA  = OFF_BP + 64 * RST * 4;      // 33792
static constexpr int STG_B    = 128 * 64 + 64 * 64;         // 12288 (A=8K,B=4K)
static constexpr int NSTAGE   = 3;
static constexpr int OFF_ACC  = OFF_MMA;                    // epilogue overlay (128*66*4=33792)
static constexpr int SMEM_TOTAL = OFF_MMA + NSTAGE * STG_B; // 70656

// scratch (no allocations allowed)
__device__ uint32_t g_Xp[(size_t)DIM_M * KW];        // bit-packed x, 2MB
__device__ uint32_t g_Wp[(size_t)DIM_N * KW];        // bit-packed W^T, 0.5MB
__device__ int8_t   g_Xb2[(size_t)DIM_M * KMMA];     // byte x, K tail, 5MB
__device__ int8_t   g_Wt2[(size_t)DIM_N * KMMA];     // byte W^T, K tail, 1.25MB

// ---------------- helpers ----------------

__device__ __forceinline__ uint32_t smem_u32(const void* p) {
    uint32_t a;
    asm("{ .reg .u64 t; cvta.to.shared.u64 t, %1; cvt.u32.u64 %0, t; }" : "=r"(a) : "l"(p));
    return a;
}
__device__ __forceinline__ constexpr int swz(int r) {   // R4-verified 16B-chunk permute
    return (r & 3) ^ ((r >> 2) & 1);
}
__device__ __forceinline__ void cp_async16(uint32_t dst, const void* src) {
    asm volatile("cp.async.cg.shared.global [%0], [%1], 16;" :: "r"(dst), "l"(src));
}
#define CP_COMMIT() asm volatile("cp.async.commit_group;" ::: "memory")
#define CP_WAIT(n)  asm volatile("cp.async.wait_group %0;" :: "n"(n) : "memory")
#define NB(id, cnt) asm volatile("bar.sync %0, %1;" :: "r"(id), "r"(cnt) : "memory")

#define LDSM_X4(r0, r1, r2, r3, addr) \
    asm volatile("ldmatrix.sync.aligned.m8n8.x4.shared.b16 {%0,%1,%2,%3}, [%4];" \
                 : "=r"(r0), "=r"(r1), "=r"(r2), "=r"(r3) : "r"(addr))

__device__ __forceinline__ void mma_s8(int* d, const uint32_t* a, const uint32_t* b) {
    asm volatile(
        "mma.sync.aligned.m16n8k32.row.col.s32.s8.s8.s32 "
        "{%0,%1,%2,%3}, {%4,%5,%6,%7}, {%8,%9}, {%0,%1,%2,%3};"
        : "+r"(d[0]), "+r"(d[1]), "+r"(d[2]), "+r"(d[3])
        : "r"(a[0]), "r"(a[1]), "r"(a[2]), "r"(a[3]), "r"(b[0]), "r"(b[1]));
}

// ---------------- profiling-alignment dummy ----------------
__global__ void dummy_kernel() {}

// ---------------- conversion kernels ----------------

// x -> bits (all K) + bytes (K tail). Block covers 8192 consecutive floats (4 rows).
__global__ void convert_x_kernel(const float* __restrict__ x) {
    const int tid = threadIdx.x;                 // 256 thr
    const int lane = tid & 31, warp = tid >> 5;
    const size_t base = (size_t)blockIdx.x * 8192;
#pragma unroll
    for (int i = 0; i < 32; ++i) {
        const size_t idx = base + (size_t)i * 256 + tid;
        float v = x[idx];
        bool neg = v < 0.0f;
        uint32_t word = __ballot_sync(0xFFFFFFFFu, neg);
        if (lane == 0) g_Xp[(base >> 5) + i * 8 + warp] = word;
        const int k = (int)(idx & (DIM_K - 1));
        if (k >= KP) {
            const size_t row = idx >> 11;
            g_Xb2[row * KMMA + (k - KP)] = neg ? (int8_t)-1 : (int8_t)1;
        }
    }
}

// W[k][n] -> Wp bits [n][kw] + Wt2 bytes [n][k-KP]
__global__ void convert_w_kernel(const float* __restrict__ W) {
    __shared__ float t[32][33];
    const int n0 = blockIdx.x * 32, k0 = blockIdx.y * 32;
    const int tx = threadIdx.x, ty = threadIdx.y;   // (32, 8)
#pragma unroll
    for (int j = 0; j < 32; j += 8)
        t[ty + j][tx] = W[(size_t)(k0 + ty + j) * DIM_N + n0 + tx];
    __syncthreads();
    const int lane = tx, w = ty;
#pragma unroll
    for (int j = 0; j < 4; ++j) {
        int nl = w * 4 + j;
        bool neg = t[lane][nl] < 0.0f;
        uint32_t word = __ballot_sync(0xFFFFFFFFu, neg);
        if (lane == 0) g_Wp[(size_t)(n0 + nl) * KW + (k0 >> 5)] = word;
        if (k0 >= KP)
            g_Wt2[(size_t)(n0 + nl) * KMMA + (k0 - KP) + lane] = neg ? (int8_t)-1 : (int8_t)1;
    }
}

// ---------------- hybrid GEMM ----------------

__global__ void __launch_bounds__(512, 1)
gemm_kernel(const float* __restrict__ bias, float* __restrict__ out) {
    extern __shared__ char smem[];
    const uint32_t sbase = smem_u32(smem);
    const int tid = threadIdx.x;
    const int m0 = blockIdx.y * BM;
    const int n0 = blockIdx.x * BN;

    if (tid < 256) {
        // ================= popc half: K in [0, KP) =================
        const int m_t = tid >> 4;      // 0..15
        const int n_t = tid & 15;      // 0..15

        // load bit tiles (KQ uint4 per row)
        for (int t = tid; t < (BM + BN) * KQ; t += 256) {
            uint32_t dst; const uint32_t* src;
            if (t < BM * KQ) {
                int r = t / KQ, c = t - r * KQ;
                dst = sbase + OFF_AP + (r * RST + c * 4) * 4;
                src = g_Xp + (size_t)(m0 + r) * KW + c * 4;
            } else {
                int u = t - BM * KQ;
                int r = u / KQ, c = u - r * KQ;
                dst = sbase + OFF_BP + (r * RST + c * 4) * 4;
                src = g_Wp + (size_t)(n0 + r) * KW + c * 4;
            }
            cp_async16(dst, src);
        }
        CP_COMMIT(); CP_WAIT(0);
        NB(1, 256);

        const uint32_t* As = reinterpret_cast<const uint32_t*>(smem + OFF_AP);
        const uint32_t* Bs = reinterpret_cast<const uint32_t*>(smem + OFF_BP);

        int acc[8][4];
#pragma unroll
        for (int mi = 0; mi < 8; ++mi)
#pragma unroll
            for (int ni = 0; ni < 4; ++ni) acc[mi][ni] = 0;

#pragma unroll 1
        for (int kq = 0; kq < KQ; ++kq) {
            uint4 b4[4];
#pragma unroll
            for (int ni = 0; ni < 4; ++ni)
                b4[ni] = *reinterpret_cast<const uint4*>(Bs + (n_t + ni * 16) * RST + kq * 4);
#pragma unroll
            for (int mi = 0; mi < 8; ++mi) {
                const uint4 a = *reinterpret_cast<const uint4*>(As + (m_t + mi * 16) * RST + kq * 4);
#pragma unroll
                for (int ni = 0; ni < 4; ++ni) {
                    acc[mi][ni] += __popc(a.x ^ b4[ni].x) + __popc(a.y ^ b4[ni].y)
                                 + __popc(a.z ^ b4[ni].z) + __popc(a.w ^ b4[ni].w);
                }
            }
        }

        NB(0, 512);   // join: mma partials now in smem

        const int* accS = reinterpret_cast<const int*>(smem + OFF_ACC);
        float bn[4];
#pragma unroll
        for (int ni = 0; ni < 4; ++ni) bn[ni] = __ldg(bias + n0 + n_t + ni * 16);
#pragma unroll
        for (int mi = 0; mi < 8; ++mi) {
            const int m = m_t + mi * 16;
            const size_t row = (size_t)(m0 + m) * DIM_N + n0;
#pragma unroll
            for (int ni = 0; ni < 4; ++ni) {
                const int n = n_t + ni * 16;
                out[row + n] = (float)(KP - 2 * acc[mi][ni] + accS[m * 66 + n]) + bn[ni];
            }
        }
    } else {
        // ================= mma half: K in [KP, 2048) =================
        const int tid2 = tid - 256;
        const int w = tid2 >> 5, l = tid2 & 31;      // w 0..7
        const int warp_m = (w >> 2) * 64;            // 2x4 warp grid: 64x16 tiles
        const int warp_n = (w & 3) * 16;

        // ldmatrix lane offsets within a stage (R4-verified; k-step1 = ^32)
        uint32_t aoff[4];
#pragma unroll
        for (int mi = 0; mi < 4; ++mi) {
            int r  = warp_m + mi * 16 + (l & 15);
            int c4 = l >> 4;
            aoff[mi] = (uint32_t)(r * 64 + ((c4 ^ swz(r)) << 4));
        }
        uint32_t boff;
        {
            int nt = (l >> 4) & 1;
            int r  = warp_n + nt * 8 + (l & 7);
            int c4 = (l >> 3) & 1;
            boff = (uint32_t)(128 * 64 + r * 64 + ((c4 ^ swz(r)) << 4));
        }

        const char* Xsrc = reinterpret_cast<const char*>(g_Xb2) + (size_t)m0 * KMMA;
        const char* Wsrc = reinterpret_cast<const char*>(g_Wt2) + (size_t)n0 * KMMA;

        auto load_stage = [&](int kt, int st) {
            const uint32_t base = sbase + OFF_MMA + st * STG_B;
            const int kb = kt * 64;
#pragma unroll
            for (int i = 0; i < 3; ++i) {
                int t = tid2 + i * 256;          // 0..767
                if (t < 512) {
                    int r = t >> 2, c = t & 3;
                    cp_async16(base + r * 64 + ((c ^ swz(r)) << 4),
                               Xsrc + (size_t)r * KMMA + kb + c * 16);
                } else {
                    int u = t - 512;
                    int r = u >> 2, c = u & 3;
                    cp_async16(base + 128 * 64 + r * 64 + ((c ^ swz(r)) << 4),
                               Wsrc + (size_t)r * KMMA + kb + c * 16);
                }
            }
        };

        load_stage(0, 0); CP_COMMIT();
        load_stage(1, 1); CP_COMMIT();

        int acc[4][2][4];
#pragma unroll
        for (int mi = 0; mi < 4; ++mi)
#pragma unroll
            for (int ni = 0; ni < 2; ++ni)
#pragma unroll
                for (int c = 0; c < 4; ++c) acc[mi][ni][c] = 0;

        for (int kt = 0; kt < NKT; ++kt) {
            CP_WAIT(1);
            NB(2, 256);
            if (kt + 2 < NKT) load_stage(kt + 2, (kt + 2) % NSTAGE);
            CP_COMMIT();

            const uint32_t stb = sbase + OFF_MMA + (kt % NSTAGE) * STG_B;
#pragma unroll
            for (int s2 = 0; s2 < 2; ++s2) {
                const uint32_t kxor = s2 * 32;
                uint32_t a[4][4], b[2][2];
#pragma unroll
                for (int mi = 0; mi < 4; ++mi)
                    LDSM_X4(a[mi][0], a[mi][1], a[mi][2], a[mi][3], stb + (aoff[mi] ^ kxor));
                {
                    uint32_t r0, r1, r2, r3;
                    LDSM_X4(r0, r1, r2, r3, stb + (boff ^ kxor));
                    b[0][0] = r0; b[0][1] = r1; b[1][0] = r2; b[1][1] = r3;
                }
#pragma unroll
                for (int mi = 0; mi < 4; ++mi)
#pragma unroll
                    for (int ni = 0; ni < 2; ++ni)
                        mma_s8(acc[mi][ni], a[mi], b[ni]);
            }
        }

        NB(2, 256);   // all mma warps done reading stages
        int* accS = reinterpret_cast<int*>(smem + OFF_ACC);
        const int g = l >> 2, tg = l & 3;
#pragma unroll
        for (int mi = 0; mi < 4; ++mi)
#pragma unroll
            for (int ni = 0; ni < 2; ++ni) {
                const int r = warp_m + mi * 16 + g;
                const int c = warp_n + ni * 8 + 2 * tg;
                accS[r * 66 + c]           = acc[mi][ni][0];
                accS[r * 66 + c + 1]       = acc[mi][ni][1];
                accS[(r + 8) * 66 + c]     = acc[mi][ni][2];
                accS[(r + 8) * 66 + c + 1] = acc[mi][ni][3];
            }

        NB(0, 512);   // join with popc half (which does the combine+store)
    }
}

// ---------------- launch ----------------

extern "C" void kernel_launch(void* const* d_in, const int* in_sizes, int n_in,
                              void* d_out, int out_size) {
    const float* x    = (const float*)d_in[0];   // [8192, 2048]
    const float* W    = (const float*)d_in[1];   // [2048, 2048]
    const float* bias = (const float*)d_in[2];   // [2048]
    float* out = (float*)d_out;                  // [8192, 2048]

    cudaFuncSetAttribute(gemm_kernel, cudaFuncAttributeMaxDynamicSharedMemorySize, SMEM_TOTAL);

    dummy_kernel<<<1, 32>>>();   // keeps ncu capture slot on gemm_kernel
    convert_x_kernel<<<(DIM_M * DIM_K) / 8192, 256>>>(x);
    convert_w_kernel<<<dim3(DIM_N / 32, DIM_K / 32), dim3(32, 8)>>>(W);
    gemm_kernel<<<dim3(DIM_N / BN, DIM_M / BM), 512, SMEM_TOTAL>>>(bias, out);
}